// round 14
// baseline (speedup 1.0000x reference)
#include <cuda_runtime.h>
#include <math.h>

// Problem constants (fixed by reference setup_inputs)
#define B_DIM 32
#define S_DIM 512
#define A_DIM 8
#define L_DIM 32
#define E_DIM 256
#define STILE 16                         // s-positions per CTA (128 threads)
#define NBLK_X (S_DIM / STILE)           // 32
#define NBLK   (B_DIM * NBLK_X)          // 1024 CTAs
#define NWARPS (NBLK * 4)                // 4096 warps
#define TAG_O 1

// Banked global accumulators: [component][bank]
__device__ float    g_bank[5][8];
__device__ unsigned g_count = 0;

__device__ __forceinline__ float ldcg_f(const float* p) {
    float v;
    asm volatile("ld.global.cg.f32 %0, [%1];" : "=f"(v) : "l"(p));
    return v;
}

__global__ __launch_bounds__(128, 8)
void ssd_loss_fused(const int*   __restrict__ input_len,
                    const float* __restrict__ conf_logits,
                    const float* __restrict__ cls_logits,
                    const float* __restrict__ reg_logits,
                    const float* __restrict__ label,
                    const int*   __restrict__ index,
                    const float* __restrict__ anchors,
                    const float* __restrict__ thr_pos_p,
                    const float* __restrict__ thr_neg_p,
                    float*       __restrict__ out)
{
    const int b    = blockIdx.y;
    const int tile = blockIdx.x;
    const int t    = threadIdx.x;        // 0..127
    const int lane = t & 31;
    const int w    = t >> 5;             // 0..3
    const int sub  = t >> 3;             // s-position within tile (0..15)

    __shared__ float s_part[128][8];     // 4KB per-(row, quarter) exp partials

    const int row0  = (b * S_DIM + tile * STILE) * A_DIM;
    const int len_b = input_len[b];

    // Warp w owns rows 32w..32w+31 = s-positions tile*16 + [4w, 4w+4).
    const bool warp_do = (tile * STILE + 4 * w) < len_b;

    // ---- Warp-local coalesced cls load + exp partials ----
    if (warp_do) {
        const float4* gw = (const float4*)cls_logits + (size_t)row0 * 8 + w * 256;
        #pragma unroll
        for (int k = 0; k < 8; k++) {
            const float4 p = gw[32 * k + lane];
            s_part[32 * w + 4 * k + (lane >> 3)][lane & 7] =
                (__expf(p.x) + __expf(p.y)) + (__expf(p.z) + __expf(p.w));
        }
    }

    // ---- Light loads ----
    const float  x    = conf_logits[row0 + t];
    const float2 an   = ((const float2*)anchors)[tile * 128 + t];  // (center, size)
    const float  thr_pos = thr_pos_p[0];
    const float  thr_neg = thr_neg_p[0];

    const float ac  = an.x;
    const float asz = an.y;
    const float al  = ac - asz * 0.5f;
    const float ar  = ac + asz * 0.5f;
    const bool  valid = (tile * STILE + sub) < len_b;

    // ---- Warp-autonomous entity gather + IOU argmax (no barriers) ----
    // Entity e = 32r + lane in round r; round/bit order == original entity order.
    float best = -1.0f;
    float bll = 0.f, blr = 0.f;
    int   bty = 0, cnt = 0;
    #pragma unroll
    for (int r = 0; r < 8; r++) {
        const int e = 32 * r + lane;
        const bool mine = (index[e] == b);
        unsigned m = __ballot_sync(0xffffffffu, mine);
        cnt += __popc(m);
        float ty = 0.f, ll = 0.f, lr = 0.f;
        if (mine) {                       // owner lane stages label (hot L1/L2)
            ty = label[3 * e + 0];
            ll = label[3 * e + 1];
            lr = label[3 * e + 2];
        }
        while (m) {
            const int j = __ffs(m) - 1;
            m &= m - 1;
            const float ell = __shfl_sync(0xffffffffu, ll, j);
            const float elr = __shfl_sync(0xffffffffu, lr, j);
            const float ety = __shfl_sync(0xffffffffu, ty, j);
            float inter = fminf(elr, ar) - fmaxf(ell, al);
            inter = fmaxf(inter, 0.0f);
            const float uni = (elr - ell) + (ar - al) - inter;
            const float iou = inter / uni;
            if (iou > best) {             // strict > : first-max tie-break
                best = iou; bll = ell; blr = elr; bty = (int)ety;
            }
        }
    }

    // Row sum for own anchor row (own warp wrote it; no cross-warp dep)
    float logsum = 0.0f;
    __syncwarp();
    if (valid) {
        const float4 r0 = *(const float4*)&s_part[t][0];
        const float4 r1 = *(const float4*)&s_part[t][4];
        const float rowsum =
            ((r0.x + r0.y) + (r0.z + r0.w)) + ((r1.x + r1.y) + (r1.z + r1.w));
        logsum = __logf(rowsum);
    }

    const bool active = valid && (cnt > 0);
    const bool pos    = active && (best >= thr_pos);
    const bool neg    = active && (best <= thr_neg);

    // ---- Confidence (BCE-with-logits, mean over ALL anchors) ----
    const float sp = fmaxf(x, 0.0f) + __logf(1.0f + __expf(-fabsf(x)));
    const float conf_term = sp - (pos ? x : 0.0f);

    // ---- Classification NLL (tv is an L1-hit scalar load from own row) ----
    float cls_nll = 0.0f;
    if (pos || neg) {
        const int target = pos ? bty : TAG_O;
        const float tv = cls_logits[(size_t)(row0 + t) * L_DIM + target];
        cls_nll = -(tv - logsum);
    }

    // ---- Regression SE on positives only ----
    float reg_se = 0.0f;
    if (pos) {
        const float lc = (bll + blr) * 0.5f;
        const float ls = blr - bll;
        const float oc = (lc - ac) / asz;
        const float os = ls / asz;
        const float r0 = reg_logits[(size_t)(row0 + t) * 2 + 0];
        const float r1 = reg_logits[(size_t)(row0 + t) * 2 + 1];
        reg_se = (r0 - oc) * (r0 - oc) + (r1 - os) * (r1 - os);
    }

    // ---- Warp reduction -> banked global atomics (no block phase) ----
    float vals[5];
    vals[0] = conf_term;
    vals[1] = cls_nll;
    vals[2] = (float)__popc(__ballot_sync(0xffffffffu, pos || neg));
    vals[3] = reg_se;
    vals[4] = (float)__popc(__ballot_sync(0xffffffffu, pos));
    #pragma unroll
    for (int j = 0; j < 5; j++) {
        float v = vals[j];
        if (j == 2 || j == 4) {
            if (lane == 0) vals[j] = v;   // counts already warp-total
            continue;
        }
        #pragma unroll
        for (int off = 16; off > 0; off >>= 1)
            v += __shfl_down_sync(0xffffffffu, v, off);
        vals[j] = v;
    }

    const int wid  = (b * NBLK_X + tile) * 4 + w;
    const int bank = wid & 7;
    if (lane == 0) {
        #pragma unroll
        for (int j = 0; j < 5; j++)
            atomicAdd(&g_bank[j][bank], vals[j]);
        __threadfence();
    }

    // ---- Per-warp ticket; last warp finishes ----
    unsigned ticket = 0;
    if (lane == 0) ticket = atomicAdd(&g_count, 1u);
    ticket = __shfl_sync(0xffffffffu, ticket, 0);
    if (ticket != NWARPS - 1) return;

    if (lane == 0) {
        float sums[5];
        #pragma unroll
        for (int j = 0; j < 5; j++) {
            float s = 0.0f;
            #pragma unroll
            for (int k = 0; k < 8; k++) s += ldcg_f(&g_bank[j][k]);
            sums[j] = s;
        }
        const float conf_loss = sums[0] / (float)(B_DIM * S_DIM * A_DIM);
        const float cls_loss  = sums[1] / sums[2];
        const float reg_loss  = sums[3] / (sums[4] * 2.0f);
        out[0] = conf_loss + cls_loss + reg_loss;
        out[1] = conf_loss;
        out[2] = cls_loss;
        out[3] = reg_loss;

        // Reset for next graph replay
        #pragma unroll
        for (int j = 0; j < 5; j++)
            #pragma unroll
            for (int k = 0; k < 8; k++) g_bank[j][k] = 0.0f;
        __threadfence();
        atomicExch(&g_count, 0u);
    }
}

extern "C" void kernel_launch(void* const* d_in, const int* in_sizes, int n_in,
                              void* d_out, int out_size)
{
    const int*   input_len   = (const int*)  d_in[0];
    const float* conf_logits = (const float*)d_in[1];
    const float* cls_logits  = (const float*)d_in[2];
    const float* reg_logits  = (const float*)d_in[3];
    const float* label       = (const float*)d_in[4];
    const int*   index       = (const int*)  d_in[5];
    const float* anchors     = (const float*)d_in[6];
    const float* thr_pos     = (const float*)d_in[7];
    const float* thr_neg     = (const float*)d_in[8];
    float* out = (float*)d_out;

    dim3 grid(NBLK_X, B_DIM);
    ssd_loss_fused<<<grid, 128>>>(input_len, conf_logits, cls_logits, reg_logits,
                                  label, index, anchors, thr_pos, thr_neg, out);
}